// round 3
// baseline (speedup 1.0000x reference)
#include <cuda_runtime.h>
#include <math.h>

#define BATCH 64
#define PLEN  128
#define DIM   1024
#define ROWS  (BATCH * PLEN)

#define WARPS_PER_BLOCK   8
#define ROWS_PER_BLOCK    WARPS_PER_BLOCK              // one row per warp
#define NBLOCKS           (ROWS / ROWS_PER_BLOCK)      // 1024
#define BLOCKS_PER_BATCH  (PLEN / ROWS_PER_BLOCK)      // 16

// Scratch: per-row score s and fc projection t, per-batch completion counters.
// Counters are reset to 0 by the finisher each call -> graph-replay safe.
__device__ float g_s[ROWS];
__device__ float g_t[ROWS];
__device__ int   g_cnt[BATCH];

__global__ void __launch_bounds__(256, 2)
fused_kernel(const float* __restrict__ h,
             const float* __restrict__ q,
             const float* __restrict__ W_att,
             const float* __restrict__ b_att,
             const float* __restrict__ W_fc,
             const float* __restrict__ b_fc,
             float* __restrict__ out) {
    const int tid  = threadIdx.x;
    const int warp = tid >> 5;
    const int lane = tid & 31;
    const int row  = blockIdx.x * ROWS_PER_BLOCK + warp;   // b*PLEN + p
    const int b    = blockIdx.x / BLOCKS_PER_BATCH;

    __shared__ float4 s_wa[512];   // W_att as float4 (8 KB)
    __shared__ float4 s_wf[512];   // W_fc  as float4 (8 KB)

    // ---- Issue all 16 data loads FIRST (front-batched, max MLP) ----
    const float4* h4 = reinterpret_cast<const float4*>(h + (size_t)row * DIM);
    const float4* q4 = reinterpret_cast<const float4*>(q + (size_t)row * DIM);

    float4 hv[8], qv[8];
    #pragma unroll
    for (int i = 0; i < 8; ++i) hv[i] = h4[lane + 32 * i];
    #pragma unroll
    for (int i = 0; i < 8; ++i) qv[i] = q4[lane + 32 * i];

    // ---- Fill weight smem (overlaps with outstanding data loads) ----
    {
        const float4* wa = reinterpret_cast<const float4*>(W_att);
        const float4* wf = reinterpret_cast<const float4*>(W_fc);
        #pragma unroll
        for (int i = 0; i < 2; ++i) {
            s_wa[tid + 256 * i] = wa[tid + 256 * i];
            s_wf[tid + 256 * i] = wf[tid + 256 * i];
        }
    }
    __syncthreads();

    // ---- Dual dot product: data from regs, weights from smem ----
    float s = 0.f, t = 0.f;
    #pragma unroll
    for (int i = 0; i < 8; ++i) {
        const int idx = lane + 32 * i;
        const float4 a = s_wa[idx];
        const float4 f = s_wf[idx];
        s += hv[i].x * a.x + hv[i].y * a.y + hv[i].z * a.z + hv[i].w * a.w;
        t += hv[i].x * f.x + hv[i].y * f.y + hv[i].z * f.z + hv[i].w * f.w;
    }
    #pragma unroll
    for (int i = 0; i < 8; ++i) {
        const int idx = 256 + lane + 32 * i;
        const float4 a = s_wa[idx];
        const float4 f = s_wf[idx];
        s += qv[i].x * a.x + qv[i].y * a.y + qv[i].z * a.z + qv[i].w * a.w;
        t += qv[i].x * f.x + qv[i].y * f.y + qv[i].z * f.z + qv[i].w * f.w;
    }

    // warp reduce (fixed order -> deterministic across replays)
    #pragma unroll
    for (int off = 16; off > 0; off >>= 1) {
        s += __shfl_xor_sync(0xffffffffu, s, off);
        t += __shfl_xor_sync(0xffffffffu, t, off);
    }
    if (lane == 0) {
        __stcg(&g_s[row], s);   // L2-scope for cross-SM visibility
        __stcg(&g_t[row], t);
    }

    // ---- Last block of each batch: softmax + pool ----
    __syncthreads();
    __threadfence();

    __shared__ int is_last;
    if (tid == 0) {
        const int old = atomicAdd(&g_cnt[b], 1);
        is_last = (old == BLOCKS_PER_BATCH - 1);
    }
    __syncthreads();
    if (!is_last) return;

    float sv = -INFINITY, tv = 0.f;
    if (tid < PLEN) {
        sv = __ldcg(&g_s[b * PLEN + tid]) + b_att[0];
        tv = __ldcg(&g_t[b * PLEN + tid]);
    }

    __shared__ float red[8];
    float m = sv;
    #pragma unroll
    for (int off = 16; off > 0; off >>= 1)
        m = fmaxf(m, __shfl_xor_sync(0xffffffffu, m, off));
    if (lane == 0) red[warp] = m;
    __syncthreads();
    float bmax = red[0];
    #pragma unroll
    for (int w = 1; w < 8; ++w) bmax = fmaxf(bmax, red[w]);
    __syncthreads();

    const float e = (tid < PLEN) ? __expf(sv - bmax) : 0.f;
    float num = e * tv;
    float den = e;
    #pragma unroll
    for (int off = 16; off > 0; off >>= 1) {
        num += __shfl_xor_sync(0xffffffffu, num, off);
        den += __shfl_xor_sync(0xffffffffu, den, off);
    }
    __shared__ float rn[8];
    __shared__ float rd[8];
    if (lane == 0) { rn[warp] = num; rd[warp] = den; }
    __syncthreads();
    if (tid == 0) {
        float N = 0.f, De = 0.f;
        #pragma unroll
        for (int w = 0; w < 8; ++w) { N += rn[w]; De += rd[w]; }
        out[b] = N / De + b_fc[0];
        g_cnt[b] = 0;           // reset for next graph replay
    }
}

extern "C" void kernel_launch(void* const* d_in, const int* in_sizes, int n_in,
                              void* d_out, int out_size) {
    const float* h     = (const float*)d_in[0];
    const float* q     = (const float*)d_in[1];
    const float* W_att = (const float*)d_in[2];
    const float* b_att = (const float*)d_in[3];
    const float* W_fc  = (const float*)d_in[4];
    const float* b_fc  = (const float*)d_in[5];
    float* out = (float*)d_out;

    fused_kernel<<<NBLOCKS, 32 * WARPS_PER_BLOCK>>>(h, q, W_att, b_att, W_fc, b_fc, out);
}

// round 4
// speedup vs baseline: 1.0017x; 1.0017x over previous
#include <cuda_runtime.h>
#include <math.h>

#define BATCH 64
#define PLEN  128
#define DIM   1024
#define ROWS  (BATCH * PLEN)

#define ROWS_PER_BLOCK    2
#define NBLOCKS           (ROWS / ROWS_PER_BLOCK)       // 4096
#define BLOCKS_PER_BATCH  (PLEN / ROWS_PER_BLOCK)       // 64

// Per-row score s and projection t; per-batch completion counters.
// Counters reset to 0 by the finisher each call -> graph-replay safe.
__device__ float g_s[ROWS];
__device__ float g_t[ROWS];
__device__ int   g_cnt[BATCH];

__global__ void __launch_bounds__(256, 4)
fused_kernel(const float* __restrict__ h,
             const float* __restrict__ q,
             const float* __restrict__ W_att,
             const float* __restrict__ b_att,
             const float* __restrict__ W_fc,
             const float* __restrict__ b_fc,
             float* __restrict__ out) {
    const int tid  = threadIdx.x;       // 0..255
    const int warp = tid >> 5;
    const int lane = tid & 31;
    const int r0   = blockIdx.x * ROWS_PER_BLOCK;   // first row of this block
    const int b    = blockIdx.x / BLOCKS_PER_BATCH;

    // ---- Front-batch the 4 data float4 loads (2 rows x h,q) ----
    const float4* h4a = reinterpret_cast<const float4*>(h + (size_t)r0 * DIM);
    const float4* q4a = reinterpret_cast<const float4*>(q + (size_t)r0 * DIM);
    const float4* h4b = reinterpret_cast<const float4*>(h + (size_t)(r0 + 1) * DIM);
    const float4* q4b = reinterpret_cast<const float4*>(q + (size_t)(r0 + 1) * DIM);

    const float4 ha = h4a[tid];
    const float4 qa = q4a[tid];
    const float4 hb = h4b[tid];
    const float4 qb = q4b[tid];

    // ---- Weight loads (L1-resident after first touch; 16 KB total) ----
    const float4* wa = reinterpret_cast<const float4*>(W_att);   // 512 float4
    const float4* wf = reinterpret_cast<const float4*>(W_fc);
    const float4 wah = wa[tid];
    const float4 waq = wa[256 + tid];
    const float4 wfh = wf[tid];
    const float4 wfq = wf[256 + tid];

    float s0 = ha.x * wah.x + ha.y * wah.y + ha.z * wah.z + ha.w * wah.w
             + qa.x * waq.x + qa.y * waq.y + qa.z * waq.z + qa.w * waq.w;
    float t0 = ha.x * wfh.x + ha.y * wfh.y + ha.z * wfh.z + ha.w * wfh.w
             + qa.x * wfq.x + qa.y * wfq.y + qa.z * wfq.z + qa.w * wfq.w;
    float s1 = hb.x * wah.x + hb.y * wah.y + hb.z * wah.z + hb.w * wah.w
             + qb.x * waq.x + qb.y * waq.y + qb.z * waq.z + qb.w * waq.w;
    float t1 = hb.x * wfh.x + hb.y * wfh.y + hb.z * wfh.z + hb.w * wfh.w
             + qb.x * wfq.x + qb.y * wfq.y + qb.z * wfq.z + qb.w * wfq.w;

    // ---- warp reduce 4 values ----
    #pragma unroll
    for (int off = 16; off > 0; off >>= 1) {
        s0 += __shfl_xor_sync(0xffffffffu, s0, off);
        t0 += __shfl_xor_sync(0xffffffffu, t0, off);
        s1 += __shfl_xor_sync(0xffffffffu, s1, off);
        t1 += __shfl_xor_sync(0xffffffffu, t1, off);
    }

    __shared__ float4 red8[8];
    if (lane == 0) red8[warp] = make_float4(s0, t0, s1, t1);
    __syncthreads();
    if (tid == 0) {
        float S0 = 0.f, T0 = 0.f, S1 = 0.f, T1 = 0.f;
        #pragma unroll
        for (int w = 0; w < 8; ++w) {
            S0 += red8[w].x; T0 += red8[w].y; S1 += red8[w].z; T1 += red8[w].w;
        }
        __stcg(&g_s[r0],     S0);
        __stcg(&g_t[r0],     T0);
        __stcg(&g_s[r0 + 1], S1);
        __stcg(&g_t[r0 + 1], T1);
    }

    // ---- Last block of each batch: softmax + pool ----
    __syncthreads();
    __threadfence();

    __shared__ int is_last;
    if (tid == 0) {
        const int old = atomicAdd(&g_cnt[b], 1);
        is_last = (old == BLOCKS_PER_BATCH - 1);
    }
    __syncthreads();
    if (!is_last) return;

    float sv = -INFINITY, tv = 0.f;
    if (tid < PLEN) {
        sv = __ldcg(&g_s[b * PLEN + tid]) + b_att[0];
        tv = __ldcg(&g_t[b * PLEN + tid]);
    }

    __shared__ float red[8];
    float m = sv;
    #pragma unroll
    for (int off = 16; off > 0; off >>= 1)
        m = fmaxf(m, __shfl_xor_sync(0xffffffffu, m, off));
    if (lane == 0) red[warp] = m;
    __syncthreads();
    float bmax = red[0];
    #pragma unroll
    for (int w = 1; w < 8; ++w) bmax = fmaxf(bmax, red[w]);
    __syncthreads();

    const float e = (tid < PLEN) ? __expf(sv - bmax) : 0.f;
    float num = e * tv;
    float den = e;
    #pragma unroll
    for (int off = 16; off > 0; off >>= 1) {
        num += __shfl_xor_sync(0xffffffffu, num, off);
        den += __shfl_xor_sync(0xffffffffu, den, off);
    }
    __shared__ float rn[8];
    __shared__ float rd[8];
    if (lane == 0) { rn[warp] = num; rd[warp] = den; }
    __syncthreads();
    if (tid == 0) {
        float N = 0.f, De = 0.f;
        #pragma unroll
        for (int w = 0; w < 8; ++w) { N += rn[w]; De += rd[w]; }
        out[b] = N / De + b_fc[0];
        g_cnt[b] = 0;   // reset for next graph replay
    }
}

extern "C" void kernel_launch(void* const* d_in, const int* in_sizes, int n_in,
                              void* d_out, int out_size) {
    const float* h     = (const float*)d_in[0];
    const float* q     = (const float*)d_in[1];
    const float* W_att = (const float*)d_in[2];
    const float* b_att = (const float*)d_in[3];
    const float* W_fc  = (const float*)d_in[4];
    const float* b_fc  = (const float*)d_in[5];
    float* out = (float*)d_out;

    fused_kernel<<<NBLOCKS, 256>>>(h, q, W_att, b_att, W_fc, b_fc, out);
}

// round 5
// speedup vs baseline: 1.2712x; 1.2691x over previous
#include <cuda_runtime.h>
#include <math.h>

#define BATCH 64
#define PLEN  128
#define DIM   1024
#define ROWS  (BATCH * PLEN)        // 8192

#define GRID1 1024
#define ITERS (ROWS / GRID1)        // 8 rows per block, stride GRID1

// Per-row attention score s and fc projection t.
__device__ float g_s[ROWS];
__device__ float g_t[ROWS];

// Kernel 1: grid-stride over rows. Weights live in registers for the whole
// block; hot loop streams h/q with depth-2 prefetch across the block reduce.
__global__ void __launch_bounds__(256, 4)
score_kernel(const float* __restrict__ h,
             const float* __restrict__ q,
             const float* __restrict__ W_att,
             const float* __restrict__ W_fc) {
    const int tid  = threadIdx.x;
    const int warp = tid >> 5;
    const int lane = tid & 31;

    // Weights in registers (one float4 per tensor-half per thread), loaded once.
    const float4* wa = reinterpret_cast<const float4*>(W_att);   // 512 float4
    const float4* wf = reinterpret_cast<const float4*>(W_fc);
    const float4 wah = wa[tid];
    const float4 waq = wa[256 + tid];
    const float4 wfh = wf[tid];
    const float4 wfq = wf[256 + tid];

    const float4* hp = reinterpret_cast<const float4*>(h);
    const float4* qp = reinterpret_cast<const float4*>(q);

    __shared__ float2 red[2][8];     // double-buffered per-warp partials

    int row = blockIdx.x;
    float4 hv = hp[(size_t)row * 256 + tid];
    float4 qv = qp[(size_t)row * 256 + tid];

    #pragma unroll
    for (int it = 0; it < ITERS; ++it) {
        // Prefetch next row while this row reduces (keeps LDGs in flight).
        float4 hn = make_float4(0.f, 0.f, 0.f, 0.f);
        float4 qn = hn;
        const int next = row + GRID1;
        if (it + 1 < ITERS) {
            hn = hp[(size_t)next * 256 + tid];
            qn = qp[(size_t)next * 256 + tid];
        }

        float s = hv.x * wah.x + hv.y * wah.y + hv.z * wah.z + hv.w * wah.w
                + qv.x * waq.x + qv.y * waq.y + qv.z * waq.z + qv.w * waq.w;
        float t = hv.x * wfh.x + hv.y * wfh.y + hv.z * wfh.z + hv.w * wfh.w
                + qv.x * wfq.x + qv.y * wfq.y + qv.z * wfq.z + qv.w * wfq.w;

        #pragma unroll
        for (int off = 16; off > 0; off >>= 1) {
            s += __shfl_xor_sync(0xffffffffu, s, off);
            t += __shfl_xor_sync(0xffffffffu, t, off);
        }
        if (lane == 0) red[it & 1][warp] = make_float2(s, t);
        __syncthreads();
        if (tid == 0) {
            float S = 0.f, T = 0.f;
            #pragma unroll
            for (int w = 0; w < 8; ++w) { S += red[it & 1][w].x; T += red[it & 1][w].y; }
            g_s[row] = S;
            g_t[row] = T;
        }
        // No second sync needed: next iteration writes the other buffer, and
        // by the time this buffer is rewritten (it+2), tid0 has passed the
        // it+1 barrier after completing its reads (program order).

        row = next;
        hv = hn;
        qv = qn;
    }
}

// Kernel 2: one block per batch. Softmax over PLEN scores, weighted sum of t.
__global__ void __launch_bounds__(PLEN)
softmax_pool_kernel(const float* __restrict__ b_att,
                    const float* __restrict__ b_fc,
                    float* __restrict__ out) {
    const int b = blockIdx.x;
    const int p = threadIdx.x;

    const float s = g_s[b * PLEN + p] + b_att[0];
    const float t = g_t[b * PLEN + p];

    const int warp = p >> 5;
    const int lane = p & 31;

    __shared__ float red[4];

    float m = s;
    #pragma unroll
    for (int off = 16; off > 0; off >>= 1)
        m = fmaxf(m, __shfl_xor_sync(0xffffffffu, m, off));
    if (lane == 0) red[warp] = m;
    __syncthreads();
    const float bmax = fmaxf(fmaxf(red[0], red[1]), fmaxf(red[2], red[3]));
    __syncthreads();

    const float e = __expf(s - bmax);
    float num = e * t;
    float den = e;
    #pragma unroll
    for (int off = 16; off > 0; off >>= 1) {
        num += __shfl_xor_sync(0xffffffffu, num, off);
        den += __shfl_xor_sync(0xffffffffu, den, off);
    }

    __shared__ float rn[4];
    __shared__ float rd[4];
    if (lane == 0) { rn[warp] = num; rd[warp] = den; }
    __syncthreads();
    if (p == 0) {
        const float N = rn[0] + rn[1] + rn[2] + rn[3];
        const float De = rd[0] + rd[1] + rd[2] + rd[3];
        out[b] = N / De + b_fc[0];
    }
}

extern "C" void kernel_launch(void* const* d_in, const int* in_sizes, int n_in,
                              void* d_out, int out_size) {
    const float* h     = (const float*)d_in[0];
    const float* q     = (const float*)d_in[1];
    const float* W_att = (const float*)d_in[2];
    const float* b_att = (const float*)d_in[3];
    const float* W_fc  = (const float*)d_in[4];
    const float* b_fc  = (const float*)d_in[5];
    float* out = (float*)d_out;

    score_kernel<<<GRID1, 256>>>(h, q, W_att, W_fc);
    softmax_pool_kernel<<<BATCH, PLEN>>>(b_att, b_fc, out);
}

// round 6
// speedup vs baseline: 1.2959x; 1.0194x over previous
#include <cuda_runtime.h>
#include <math.h>

#define BATCH 64
#define PLEN  128
#define DIM   1024
#define ROWS  (BATCH * PLEN)        // 8192

#define GRID1 1024
#define ITERS (ROWS / GRID1)        // 8 rows per block, stride GRID1

// Per-row attention score s and fc projection t.
__device__ float g_s[ROWS];
__device__ float g_t[ROWS];

// Kernel 1: grid-stride over rows. Weights live in registers for the whole
// block; hot loop streams h/q with depth-2 prefetch across the block reduce.
__global__ void __launch_bounds__(256, 4)
score_kernel(const float* __restrict__ h,
             const float* __restrict__ q,
             const float* __restrict__ W_att,
             const float* __restrict__ W_fc) {
    const int tid  = threadIdx.x;
    const int warp = tid >> 5;
    const int lane = tid & 31;

    const float4* wa = reinterpret_cast<const float4*>(W_att);   // 512 float4
    const float4* wf = reinterpret_cast<const float4*>(W_fc);
    const float4 wah = wa[tid];
    const float4 waq = wa[256 + tid];
    const float4 wfh = wf[tid];
    const float4 wfq = wf[256 + tid];

    const float4* hp = reinterpret_cast<const float4*>(h);
    const float4* qp = reinterpret_cast<const float4*>(q);

    __shared__ float2 red[2][8];     // double-buffered per-warp partials

    int row = blockIdx.x;
    float4 hv = hp[(size_t)row * 256 + tid];
    float4 qv = qp[(size_t)row * 256 + tid];

    #pragma unroll
    for (int it = 0; it < ITERS; ++it) {
        float4 hn = make_float4(0.f, 0.f, 0.f, 0.f);
        float4 qn = hn;
        const int next = row + GRID1;
        if (it + 1 < ITERS) {
            hn = hp[(size_t)next * 256 + tid];
            qn = qp[(size_t)next * 256 + tid];
        }

        float s = hv.x * wah.x + hv.y * wah.y + hv.z * wah.z + hv.w * wah.w
                + qv.x * waq.x + qv.y * waq.y + qv.z * waq.z + qv.w * waq.w;
        float t = hv.x * wfh.x + hv.y * wfh.y + hv.z * wfh.z + hv.w * wfh.w
                + qv.x * wfq.x + qv.y * wfq.y + qv.z * wfq.z + qv.w * wfq.w;

        #pragma unroll
        for (int off = 16; off > 0; off >>= 1) {
            s += __shfl_xor_sync(0xffffffffu, s, off);
            t += __shfl_xor_sync(0xffffffffu, t, off);
        }
        if (lane == 0) red[it & 1][warp] = make_float2(s, t);
        __syncthreads();
        if (tid == 0) {
            float S = 0.f, T = 0.f;
            #pragma unroll
            for (int w = 0; w < 8; ++w) { S += red[it & 1][w].x; T += red[it & 1][w].y; }
            g_s[row] = S;
            g_t[row] = T;
        }
        row = next;
        hv = hn;
        qv = qn;
    }

    // PDL: this block's contribution to g_s/g_t is done (stores above are
    // in program order before the trigger). When all blocks have triggered,
    // the dependent softmax kernel may launch.
    cudaTriggerProgrammaticLaunchCompletion();
}

// Kernel 2: one WARP per batch. Pure shuffle reductions, no smem, no barriers.
// Launched with programmatic stream serialization; waits on kernel 1's data
// via cudaGridDependencySynchronize().
__global__ void __launch_bounds__(32)
softmax_pool_kernel(const float* __restrict__ b_att,
                    const float* __restrict__ b_fc,
                    float* __restrict__ out) {
    cudaGridDependencySynchronize();

    const int b    = blockIdx.x;
    const int lane = threadIdx.x;

    const float4 sv = *reinterpret_cast<const float4*>(&g_s[b * PLEN + lane * 4]);
    const float4 tv = *reinterpret_cast<const float4*>(&g_t[b * PLEN + lane * 4]);

    // max over the 4 local values, then warp max (b_att is a uniform shift:
    // fold it in after the max — exp(s+ba - (m+ba)) == exp(s-m), and the
    // +ba cancels entirely in num/den, so we can ignore b_att altogether).
    float m = fmaxf(fmaxf(sv.x, sv.y), fmaxf(sv.z, sv.w));
    #pragma unroll
    for (int off = 16; off > 0; off >>= 1)
        m = fmaxf(m, __shfl_xor_sync(0xffffffffu, m, off));

    const float e0 = __expf(sv.x - m);
    const float e1 = __expf(sv.y - m);
    const float e2 = __expf(sv.z - m);
    const float e3 = __expf(sv.w - m);

    float num = e0 * tv.x + e1 * tv.y + e2 * tv.z + e3 * tv.w;
    float den = e0 + e1 + e2 + e3;
    #pragma unroll
    for (int off = 16; off > 0; off >>= 1) {
        num += __shfl_xor_sync(0xffffffffu, num, off);
        den += __shfl_xor_sync(0xffffffffu, den, off);
    }

    if (lane == 0) out[b] = num / den + b_fc[0];
    (void)b_att;   // cancels in the softmax ratio
}

extern "C" void kernel_launch(void* const* d_in, const int* in_sizes, int n_in,
                              void* d_out, int out_size) {
    const float* h     = (const float*)d_in[0];
    const float* q     = (const float*)d_in[1];
    const float* W_att = (const float*)d_in[2];
    const float* b_att = (const float*)d_in[3];
    const float* W_fc  = (const float*)d_in[4];
    const float* b_fc  = (const float*)d_in[5];
    float* out = (float*)d_out;

    score_kernel<<<GRID1, 256>>>(h, q, W_att, W_fc);

    // Dependent launch with programmatic serialization (PDL): overlaps this
    // kernel's launch latency with score_kernel's tail.
    cudaLaunchConfig_t cfg = {};
    cfg.gridDim  = dim3(BATCH, 1, 1);
    cfg.blockDim = dim3(32, 1, 1);
    cfg.dynamicSmemBytes = 0;
    cfg.stream = 0;
    cudaLaunchAttribute attrs[1];
    attrs[0].id = cudaLaunchAttributeProgrammaticStreamSerialization;
    attrs[0].val.programmaticStreamSerializationAllowed = 1;
    cfg.attrs = attrs;
    cfg.numAttrs = 1;
    cudaLaunchKernelEx(&cfg, softmax_pool_kernel, b_att, b_fc, out);
}